// round 9
// baseline (speedup 1.0000x reference)
#include <cuda_runtime.h>
#include <cuda_bf16.h>

typedef unsigned long long ull;

// ---------------- packed f32x2 helpers (sm_103a) ----------------
__device__ __forceinline__ ull pk2(float a, float b){
    ull r; asm("mov.b64 %0,{%1,%2};" : "=l"(r) : "f"(a), "f"(b)); return r;
}
__device__ __forceinline__ void upk2(ull v, float& a, float& b){
    asm("mov.b64 {%0,%1},%2;" : "=f"(a), "=f"(b) : "l"(v));
}
__device__ __forceinline__ ull mul2(ull a, ull b){
    ull r; asm("mul.rn.f32x2 %0,%1,%2;" : "=l"(r) : "l"(a), "l"(b)); return r;
}
__device__ __forceinline__ void fma2(ull& d, ull a, ull b){
    asm("fma.rn.f32x2 %0,%1,%2,%0;" : "+l"(d) : "l"(a), "l"(b));
}
__device__ __forceinline__ void lds2u64(unsigned a, ull& x, ull& y){
    asm volatile("ld.shared.v2.b64 {%0,%1},[%2];" : "=l"(x), "=l"(y) : "r"(a));
}
__device__ __forceinline__ void lds1u64(unsigned a, ull& x){
    asm volatile("ld.shared.b64 %0,[%1];" : "=l"(x) : "r"(a));
}
__device__ __forceinline__ void sts2u64(unsigned a, ull x, ull y){
    asm volatile("st.shared.v2.b64 [%0],{%1,%2};" :: "r"(a), "l"(x), "l"(y));
}
__device__ __forceinline__ void sts1u64(unsigned a, ull x){
    asm volatile("st.shared.b64 [%0],%1;" :: "r"(a), "l"(x));
}

// Tile: 4 rows x 32 cols x all 64 channels. 512 threads = 16 warps.
// smem layout (float offsets):
//   xs  [0      .. 15360)  halo: xs[c][r][s] = c*240 + r*40 + s  (s=3..36 used)
//   Hs  [15360  .. 23552)  h tile (ull pairs): Hs[o][2L..2L+1], o-stride 512B
//   w2s [23552  .. 44032)  per-ci packed dup weights: [cl][j][oo] 16B chunks
//   w1d [44032  .. 52224)  packed dup w1: [cc][g][w16] 16B chunks
#define XS_OFF   0
#define HS_OFF   15360
#define W2S_OFF  23552
#define W1D_OFF  44032
#define SMEM_FLOATS 52224
#define SMEM_BYTES  (SMEM_FLOATS*4)

__global__ void __launch_bounds__(512, 1)
invol_kernel(const float* __restrict__ x, const float* __restrict__ w1,
             const float* __restrict__ w2, float* __restrict__ out)
{
    extern __shared__ float sm[];
    const unsigned su = (unsigned)__cvta_generic_to_shared(sm);

    const int tid = threadIdx.x;
    const int L   = tid & 31;
    const int wid = tid >> 5;
    const int w0  = blockIdx.x * 32;
    const int h0  = blockIdx.y * 4;
    const int b   = blockIdx.z;

    const int ro = L >> 3;            // lane's tile row (0..3)
    const int cb = (L & 7) * 4;       // lane's tile col base (0..28)

    const float* xb = x + (size_t)b * 64 * 224 * 224;

    // ---------------- Stage A: 64c x 6r x 34col halo into xs ----------------
    for (int row = wid; row < 384; row += 16) {
        int c = row / 6, r = row - 6 * c;
        int gr = h0 - 1 + r;
        bool rok = ((unsigned)gr < 224u);
        const float* src = xb + ((size_t)c * 224 + gr) * 224;
        float* dst = sm + c * 240 + r * 40 + 3;
        #pragma unroll
        for (int ii = 0; ii < 2; ++ii) {
            int i = L + 32 * ii;
            if (i < 34) {
                int g = w0 - 1 + i;
                dst[i] = (rok && (unsigned)g < 224u) ? __ldg(src + g) : 0.0f;
            }
        }
    }

    // ---------------- Stage W1d: pack duplicated w1 pairs -------------------
    // chunk [cc][g][w16] = { dup(w1[(w16+32g)*64+cc]), dup(w1[(w16+32g+16)*64+cc]) }
    #pragma unroll
    for (int t = 0; t < 4; ++t) {
        int u = tid + 512 * t;          // 2048 units
        int w16 = u & 15;
        int g   = (u >> 4) & 1;
        int cc  = u >> 5;
        int o0 = w16 + 32 * g, o1 = o0 + 16;
        float a = __ldg(w1 + o0 * 64 + cc);
        float c2 = __ldg(w1 + o1 * 64 + cc);
        sts2u64(su + (W1D_OFF + cc * 128 + g * 64 + w16 * 4) * 4,
                pk2(a, a), pk2(c2, c2));
    }
    __syncthreads();

    // ---------------- Stage B: h[o,p] = relu(sum_c w1[o,c]*x[c,p]) ----------
    // warp wid -> o in {wid, wid+16, wid+32, wid+48}; lane = 4 pixels
    const unsigned xrow   = su + ((ro + 1) * 40 + 4 + cb) * 4;   // c-stride 960B
    const unsigned w1base = su + W1D_OFF * 4 + wid * 16;
    ull hA[4], hB[4];
    #pragma unroll
    for (int oi = 0; oi < 4; ++oi) { hA[oi] = 0ull; hB[oi] = 0ull; }

    #pragma unroll 8
    for (int cc = 0; cc < 64; ++cc) {
        ull xA, xB;   lds2u64(xrow + cc * 960, xA, xB);            // xs c-stride = 240 floats
        ull wA0, wA1; lds2u64(w1base + cc * 512, wA0, wA1);        // o=wid, wid+16
        ull wB0, wB1; lds2u64(w1base + cc * 512 + 256, wB0, wB1);  // o=wid+32, wid+48
        fma2(hA[0], wA0, xA); fma2(hB[0], wA0, xB);
        fma2(hA[1], wA1, xA); fma2(hB[1], wA1, xB);
        fma2(hA[2], wB0, xA); fma2(hB[2], wB0, xB);
        fma2(hA[3], wB1, xA); fma2(hB[3], wB1, xB);
    }
    #pragma unroll
    for (int oi = 0; oi < 4; ++oi) {
        int o = wid + 16 * oi;
        float a0, a1, a2, a3;
        upk2(hA[oi], a0, a1); upk2(hB[oi], a2, a3);
        a0 = fmaxf(a0, 0.0f); a1 = fmaxf(a1, 0.0f);
        a2 = fmaxf(a2, 0.0f); a3 = fmaxf(a3, 0.0f);
        sts2u64(su + HS_OFF * 4 + (o * 64 + 2 * L) * 8, pk2(a0, a1), pk2(a2, a3));
    }

    // ---------------- Stage C: 4 ci stages of 16 channels each --------------
    const unsigned hs_base = su + HS_OFF * 4 + L * 16;
    const unsigned w2s     = su + W2S_OFF * 4;

    #pragma unroll 1
    for (int ci = 0; ci < 4; ++ci) {
        // stage packed dup w2 pairs for channels c = ci*16 + cl
        // chunk [cl][j][oo]: j<4 -> {dup(w2[(c*9+2j)*64+oo]), dup(w2[..2j+1..])}
        #pragma unroll
        for (int t = 0; t < 10; ++t) {
            int u = tid + 512 * t;        // 5120 units
            int oo = u & 63;
            int r  = u >> 6;              // 0..79
            int j  = r % 5;
            int cl = r / 5;
            int c  = ci * 16 + cl;
            const float* wsrc = w2 + (size_t)(c * 9) * 64 + oo;
            unsigned a = w2s + cl * 5120 + j * 1024 + oo * 16;
            if (j < 4) {
                float v0 = __ldg(wsrc + (2 * j) * 64);
                float v1 = __ldg(wsrc + (2 * j + 1) * 64);
                sts2u64(a, pk2(v0, v0), pk2(v1, v1));
            } else {
                float v = __ldg(wsrc + 8 * 64);
                sts1u64(a, pk2(v, v));
            }
        }
        __syncthreads();   // staging done; also guards Hs ready on ci=0

        const int c = ci * 16 + wid;

        // patches: rows ro..ro+2, 6 taps each; packs P[i][m]=(v[m],v[m+1])
        ull P[3][5];
        #pragma unroll
        for (int i = 0; i < 3; ++i) {
            const float* pr = sm + c * 240 + (ro + i) * 40 + 3 + cb;
            float v0 = pr[0], v1 = pr[1], v2 = pr[2];
            float v3 = pr[3], v4 = pr[4], v5 = pr[5];
            P[i][0] = pk2(v0, v1); P[i][1] = pk2(v1, v2); P[i][2] = pk2(v2, v3);
            P[i][3] = pk2(v3, v4); P[i][4] = pk2(v4, v5);
        }

        ull accA = 0ull, accB = 0ull;
        const unsigned wb = w2s + wid * 5120;

        #pragma unroll 8
        for (int oo = 0; oo < 64; ++oo) {
            ull hhA, hhB; lds2u64(hs_base + oo * 512, hhA, hhB);
            ull k0, k1;   lds2u64(wb + oo * 16,        k0, k1);
            ull k2, k3;   lds2u64(wb + 1024 + oo * 16, k2, k3);
            ull k4, k5;   lds2u64(wb + 2048 + oo * 16, k4, k5);
            ull k6, k7;   lds2u64(wb + 3072 + oo * 16, k6, k7);
            ull k8;       lds1u64(wb + 4096 + oo * 16, k8);

            ull tA = mul2(k0, P[0][0]); ull tB = mul2(k0, P[0][2]);
            fma2(tA, k1, P[0][1]);      fma2(tB, k1, P[0][3]);
            fma2(tA, k2, P[0][2]);      fma2(tB, k2, P[0][4]);
            fma2(tA, k3, P[1][0]);      fma2(tB, k3, P[1][2]);
            fma2(tA, k4, P[1][1]);      fma2(tB, k4, P[1][3]);
            fma2(tA, k5, P[1][2]);      fma2(tB, k5, P[1][4]);
            fma2(tA, k6, P[2][0]);      fma2(tB, k6, P[2][2]);
            fma2(tA, k7, P[2][1]);      fma2(tB, k7, P[2][3]);
            fma2(tA, k8, P[2][2]);      fma2(tB, k8, P[2][4]);
            fma2(accA, hhA, tA);        fma2(accB, hhB, tB);
        }

        float o0, o1, o2, o3;
        upk2(accA, o0, o1); upk2(accB, o2, o3);
        float4 ov; ov.x = o0; ov.y = o1; ov.z = o2; ov.w = o3;
        size_t obase = (((size_t)(b * 64 + c) * 224 + (h0 + ro)) * 224) + (w0 + cb);
        *(float4*)(out + obase) = ov;

        __syncthreads();   // all reads of w2s/Hs done before next staging
    }
}

extern "C" void kernel_launch(void* const* d_in, const int* in_sizes, int n_in,
                              void* d_out, int out_size)
{
    const float* x  = (const float*)d_in[0];   // (4,64,224,224)
    const float* w1 = (const float*)d_in[1];   // (64,64)
    const float* w2 = (const float*)d_in[2];   // (576,64)
    float* out = (float*)d_out;                // (4,64,224,224)

    cudaFuncSetAttribute(invol_kernel,
                         cudaFuncAttributeMaxDynamicSharedMemorySize, SMEM_BYTES);
    dim3 grid(224 / 32, 224 / 4, 4);           // 7 x 56 x 4 = 1568 blocks
    invol_kernel<<<grid, 512, SMEM_BYTES>>>(x, w1, w2, out);
}

// round 11
// speedup vs baseline: 1.1043x; 1.1043x over previous
#include <cuda_runtime.h>
#include <cuda_bf16.h>

typedef unsigned long long ull;

// ---------------- packed f32x2 helpers (sm_103a) ----------------
__device__ __forceinline__ ull pk2(float a, float b){
    ull r; asm("mov.b64 %0,{%1,%2};" : "=l"(r) : "f"(a), "f"(b)); return r;
}
__device__ __forceinline__ void upk2(ull v, float& a, float& b){
    asm("mov.b64 {%0,%1},%2;" : "=f"(a), "=f"(b) : "l"(v));
}
__device__ __forceinline__ ull mul2(ull a, ull b){
    ull r; asm("mul.rn.f32x2 %0,%1,%2;" : "=l"(r) : "l"(a), "l"(b)); return r;
}
__device__ __forceinline__ void fma2(ull& d, ull a, ull b){
    asm("fma.rn.f32x2 %0,%1,%2,%0;" : "+l"(d) : "l"(a), "l"(b));
}
__device__ __forceinline__ void lds2u64(unsigned a, ull& x, ull& y){
    asm volatile("ld.shared.v2.b64 {%0,%1},[%2];" : "=l"(x), "=l"(y) : "r"(a));
}
__device__ __forceinline__ void lds1u64(unsigned a, ull& x){
    asm volatile("ld.shared.b64 %0,[%1];" : "=l"(x) : "r"(a));
}
__device__ __forceinline__ void sts2u64(unsigned a, ull x, ull y){
    asm volatile("st.shared.v2.b64 [%0],{%1,%2};" :: "r"(a), "l"(x), "l"(y));
}
__device__ __forceinline__ void sts1u64(unsigned a, ull x){
    asm volatile("st.shared.b64 [%0],%1;" :: "r"(a), "l"(x));
}

// Tile: 4 rows x 32 cols x all 64 channels. 512 threads = 16 warps.
// smem (float offsets):
//   xs  [0     .. 15616)  halo: xs[c][r][s] = c*244 + r*40 + s  (6 rows, s=3..36)
//   Hs  [15616 .. 32000)  dup h pairs: ull at o*128 + px   (64 KB)
//        (reused at end as res[c*133 + px] transpose buffer)
//   w2p [32000 .. 42368)  chunk of channel-pair weights: ull at cp*162 + oc*10 + k
//   w1d [42368 .. 50560)  packed dup w1: [cc][g][w16] 16B chunks (8192 floats)
#define XS_STRIDE 244
#define HS_OFF   15616
#define W2P_OFF  32000
#define W1D_OFF  42368
#define SMEM_FLOATS 50560
#define SMEM_BYTES  (SMEM_FLOATS*4)

// 9-tap sum for one pixel: rows T[R0..R2], col window starting at J
#define TAPSUM(t, R0, R1, R2, J) \
    t = mul2(w0_, T[R0][J]);   fma2(t, w1_, T[R0][(J)+1]); fma2(t, w2_, T[R0][(J)+2]); \
    fma2(t, w3_, T[R1][J]);    fma2(t, w4_, T[R1][(J)+1]); fma2(t, w5_, T[R1][(J)+2]); \
    fma2(t, w6_, T[R2][J]);    fma2(t, w7_, T[R2][(J)+1]); fma2(t, w8_, T[R2][(J)+2]);

__global__ void __launch_bounds__(512, 1)
invol_kernel(const float* __restrict__ x, const float* __restrict__ w1,
             const float* __restrict__ w2, float* __restrict__ out)
{
    extern __shared__ float sm[];
    const unsigned su = (unsigned)__cvta_generic_to_shared(sm);

    const int tid = threadIdx.x;
    const int L   = tid & 31;
    const int wid = tid >> 5;
    const int w0c = blockIdx.x * 32;
    const int h0  = blockIdx.y * 4;
    const int b   = blockIdx.z;

    const float* xb = x + (size_t)b * 64 * 224 * 224;

    // ---------------- Stage A: 64c x 6r x 34col halo into xs ----------------
    for (int row = wid; row < 384; row += 16) {
        int c = row / 6, r = row - 6 * c;
        int gr = h0 - 1 + r;
        bool rok = ((unsigned)gr < 224u);
        const float* src = xb + ((size_t)c * 224 + gr) * 224;
        float* dst = sm + c * XS_STRIDE + r * 40 + 3;
        #pragma unroll
        for (int ii = 0; ii < 2; ++ii) {
            int i = L + 32 * ii;
            if (i < 34) {
                int g = w0c - 1 + i;
                dst[i] = (rok && (unsigned)g < 224u) ? __ldg(src + g) : 0.0f;
            }
        }
    }

    // ---------------- Stage W1d: pack duplicated w1 pairs -------------------
    #pragma unroll
    for (int t = 0; t < 4; ++t) {
        int u = tid + 512 * t;
        int w16 = u & 15;
        int g   = (u >> 4) & 1;
        int cc  = u >> 5;
        int o0 = w16 + 32 * g, o1 = o0 + 16;
        float a = __ldg(w1 + o0 * 64 + cc);
        float c2 = __ldg(w1 + o1 * 64 + cc);
        sts2u64(su + (W1D_OFF + cc * 128 + g * 64 + w16 * 4) * 4,
                pk2(a, a), pk2(c2, c2));
    }
    __syncthreads();

    // ---------------- Stage B: h[o,p] = relu(sum_c w1[o,c]*x[c,p]) ----------
    {
        const int ro = L >> 3;
        const int cb = (L & 7) * 4;
        const unsigned xrow   = su + ((ro + 1) * 40 + 4 + cb) * 4;   // + c*976
        const unsigned w1base = su + W1D_OFF * 4 + wid * 16;
        ull hA[4], hB[4];
        #pragma unroll
        for (int oi = 0; oi < 4; ++oi) { hA[oi] = 0ull; hB[oi] = 0ull; }

        #pragma unroll 8
        for (int cc = 0; cc < 64; ++cc) {
            ull xA, xB;   lds2u64(xrow + cc * (XS_STRIDE*4), xA, xB);
            ull wA0, wA1; lds2u64(w1base + cc * 512, wA0, wA1);
            ull wB0, wB1; lds2u64(w1base + cc * 512 + 256, wB0, wB1);
            fma2(hA[0], wA0, xA); fma2(hB[0], wA0, xB);
            fma2(hA[1], wA1, xA); fma2(hB[1], wA1, xB);
            fma2(hA[2], wB0, xA); fma2(hB[2], wB0, xB);
            fma2(hA[3], wB1, xA); fma2(hB[3], wB1, xB);
        }
        const unsigned HSb = su + HS_OFF * 4;
        #pragma unroll
        for (int oi = 0; oi < 4; ++oi) {
            int o = wid + 16 * oi;
            float a0, a1, a2, a3;
            upk2(hA[oi], a0, a1); upk2(hB[oi], a2, a3);
            a0 = fmaxf(a0, 0.0f); a1 = fmaxf(a1, 0.0f);
            a2 = fmaxf(a2, 0.0f); a3 = fmaxf(a3, 0.0f);
            unsigned base = HSb + (o * 128 + ro * 32 + cb) * 8;
            sts2u64(base,      pk2(a0, a0), pk2(a1, a1));
            sts2u64(base + 16, pk2(a2, a2), pk2(a3, a3));
        }
    }

    // ---------------- Stage C -----------------------------------------------
    // warp -> 2 rows x 4 cols of pixels; lane -> channel pair (2L, 2L+1)
    const int rp  = (wid & 1) * 2;
    const int cwb = (wid >> 1) * 4;

    // tap pairs: T[i][m] = (x[c0, halo row rp+i, tap col m], x[c1, ...])
    // pixel j's taps live at halo offsets 3+j, 4+j, 5+j  (j = cwb+dq)
    ull T[4][6];
    #pragma unroll
    for (int i = 0; i < 4; ++i) {
        const float* pr0 = sm + (2 * L) * XS_STRIDE + (rp + i) * 40 + 3 + cwb;
        const float* pr1 = pr0 + XS_STRIDE;
        #pragma unroll
        for (int m = 0; m < 6; ++m) T[i][m] = pk2(pr0[m], pr1[m]);
    }

    ull acc[2][4];
    #pragma unroll
    for (int dr = 0; dr < 2; ++dr)
        #pragma unroll
        for (int dq = 0; dq < 4; ++dq) acc[dr][dq] = 0ull;

    const unsigned HSb  = su + HS_OFF * 4;
    const unsigned W2Pb = su + W2P_OFF * 4;

    #pragma unroll 1
    for (int och = 0; och < 4; ++och) {
        if (och) __syncthreads();         // prev chunk reads complete
        // stage w2 chunk: 4608 ull = (32 cp) x (16 oc) x (9 k)
        #pragma unroll
        for (int t = 0; t < 9; ++t) {
            int u = tid + 512 * t;
            int oc = u & 15;
            int rest = u >> 4;            // 0..287
            int cp = rest / 9;
            int k  = rest - cp * 9;
            const float* p = w2 + (size_t)(cp * 18 + k) * 64 + (och * 16 + oc);
            float v0 = __ldg(p);
            float v1 = __ldg(p + 576);    // channel 2cp+1 -> +9*64
            sts1u64(W2Pb + (cp * 162 + oc * 10 + k) * 8, pk2(v0, v1));
        }
        __syncthreads();                  // chunk staged (och=0: also Hs ready)

        unsigned hb = HSb + ((och * 16) * 128 + rp * 32 + cwb) * 8;
        unsigned wb = W2Pb + (L * 162) * 8;

        #pragma unroll 1
        for (int oc = 0; oc < 16; ++oc) {
            ull w0_, w1_, w2_, w3_, w4_, w5_, w6_, w7_, w8_;
            lds2u64(wb +  0, w0_, w1_);
            lds2u64(wb + 16, w2_, w3_);
            lds2u64(wb + 32, w4_, w5_);
            lds2u64(wb + 48, w6_, w7_);
            lds1u64(wb + 64, w8_);
            wb += 80;
            ull hA0, hA1, hA2, hA3, hB0, hB1, hB2, hB3;
            lds2u64(hb,            hA0, hA1);
            lds2u64(hb + 16,       hA2, hA3);
            lds2u64(hb + 256,      hB0, hB1);
            lds2u64(hb + 256 + 16, hB2, hB3);
            hb += 1024;

            ull t;
            TAPSUM(t, 0, 1, 2, 0); fma2(acc[0][0], hA0, t);
            TAPSUM(t, 0, 1, 2, 1); fma2(acc[0][1], hA1, t);
            TAPSUM(t, 0, 1, 2, 2); fma2(acc[0][2], hA2, t);
            TAPSUM(t, 0, 1, 2, 3); fma2(acc[0][3], hA3, t);
            TAPSUM(t, 1, 2, 3, 0); fma2(acc[1][0], hB0, t);
            TAPSUM(t, 1, 2, 3, 1); fma2(acc[1][1], hB1, t);
            TAPSUM(t, 1, 2, 3, 2); fma2(acc[1][2], hB2, t);
            TAPSUM(t, 1, 2, 3, 3); fma2(acc[1][3], hB3, t);
        }
    }

    // ---------------- Output: transpose through smem, coalesced store -------
    __syncthreads();                      // all Hs reads done before overwrite
    #pragma unroll
    for (int dr = 0; dr < 2; ++dr)
        #pragma unroll
        for (int dq = 0; dq < 4; ++dq) {
            float lo, hi; upk2(acc[dr][dq], lo, hi);
            int px = (rp + dr) * 32 + cwb + dq;
            sm[HS_OFF + (2 * L) * 133 + px]     = lo;
            sm[HS_OFF + (2 * L + 1) * 133 + px] = hi;
        }
    __syncthreads();
    {
        int seg  = tid >> 1;              // 0..255 = (c, row)
        int c    = seg >> 2;
        int row  = seg & 3;
        int colb = (tid & 1) * 16;
        const float* rsrc = sm + HS_OFF + c * 133 + row * 32 + colb;
        float* og = out + (((size_t)(b * 64 + c) * 224) + (h0 + row)) * 224
                        + w0c + colb;
        #pragma unroll
        for (int j = 0; j < 4; ++j) {
            float4 v;
            v.x = rsrc[4 * j];     v.y = rsrc[4 * j + 1];
            v.z = rsrc[4 * j + 2]; v.w = rsrc[4 * j + 3];
            *(float4*)(og + 4 * j) = v;
        }
    }
}

extern "C" void kernel_launch(void* const* d_in, const int* in_sizes, int n_in,
                              void* d_out, int out_size)
{
    const float* x  = (const float*)d_in[0];   // (4,64,224,224)
    const float* w1 = (const float*)d_in[1];   // (64,64)
    const float* w2 = (const float*)d_in[2];   // (576,64)
    float* out = (float*)d_out;                // (4,64,224,224)

    cudaFuncSetAttribute(invol_kernel,
                         cudaFuncAttributeMaxDynamicSharedMemorySize, SMEM_BYTES);
    dim3 grid(224 / 32, 224 / 4, 4);           // 7 x 56 x 4 = 1568 blocks
    invol_kernel<<<grid, 512, SMEM_BYTES>>>(x, w1, w2, out);
}